// round 15
// baseline (speedup 1.0000x reference)
#include <cuda_runtime.h>
#include <cstdint>

// Problem constants
#define SS 7
#define CC 20
#define PSTR 30          // pred floats per cell  (2*5 + 20)
#define TSTR 25          // target floats per cell (20 + 1 + 4)
#define BATCH 8192
#define NCELL (BATCH * SS * SS)      // 401408
#define BLOCK 128
#define NCHUNK (NCELL / BLOCK)       // 3136 (exact)
#define PRED4_PER_CHUNK (BLOCK * PSTR / 4)   // 960
#define TARG4_PER_CHUNK (BLOCK * TSTR / 4)   // 800
// 592 = 4 x 148: exactly 4 blocks co-resident per SM (4 x 56.3KB = 225KB of
// 228KB smem). More resident blocks stagger compute/barrier phases and keep
// +33% more bytes in flight during compute windows vs 3/SM.
// 3136 = 592*5 + 176: first 176 blocks take 6 contiguous chunks, the rest 5.
// Per-SM totals land at 21-22 chunks (same imbalance as the 444 schedule).
#define GRID 592
#define NEXTRA 176                   // blocks with 6 chunks

// global accumulators: loss, sum(iou*obj), sum(obj).
// Zero at module load; last block resets after finalize -> graph-replayable.
__device__ float g_acc[3];
__device__ unsigned int g_count;

// 16B async copy with 256B L2 prefetch hint (sequential stream friendly)
__device__ __forceinline__ void cp_async16(void* smem_dst, const void* gmem_src) {
    uint32_t s = (uint32_t)__cvta_generic_to_shared(smem_dst);
    asm volatile("cp.async.cg.shared.global.L2::256B [%0], [%1], 16;\n"
                 :: "r"(s), "l"(gmem_src));
}
__device__ __forceinline__ void cp_commit() {
    asm volatile("cp.async.commit_group;\n" ::: "memory");
}
template <int N>
__device__ __forceinline__ void cp_wait() {
    asm volatile("cp.async.wait_group %0;\n" :: "n"(N) : "memory");
}

// single-instruction MUFU approximations (flag-independent)
__device__ __forceinline__ float fsqrt_approx(float x) {
    float r;
    asm("sqrt.approx.f32 %0, %1;" : "=f"(r) : "f"(x));
    return r;
}
__device__ __forceinline__ float frcp_approx(float x) {
    float r;
    asm("rcp.approx.f32 %0, %1;" : "=f"(r) : "f"(x));
    return r;
}

struct __align__(16) Stage {
    float sp[BLOCK * PSTR];   // 15360 B
    float st[BLOCK * TSTR];   // 12800 B
};

__device__ __forceinline__ void stage_chunk(Stage& buf, int chunk,
                                            const float4* __restrict__ pred4,
                                            const float4* __restrict__ targ4,
                                            int tid) {
    const float4* pc = pred4 + (size_t)chunk * PRED4_PER_CHUNK;
    const float4* tc = targ4 + (size_t)chunk * TARG4_PER_CHUNK;
    float4* sp4 = reinterpret_cast<float4*>(buf.sp);
    float4* st4 = reinterpret_cast<float4*>(buf.st);
    #pragma unroll
    for (int i = tid; i < PRED4_PER_CHUNK; i += BLOCK)
        cp_async16(&sp4[i], &pc[i]);
    #pragma unroll
    for (int i = tid; i < TARG4_PER_CHUNK; i += BLOCK)
        cp_async16(&st4[i], &tc[i]);
    cp_commit();
}

// intersection area of two xywh boxes (no division)
__device__ __forceinline__ float inter_area(float ax, float ay, float aw, float ah,
                                            float bx, float by, float bw, float bh) {
    float ax1 = ax - aw * 0.5f, ax2 = ax + aw * 0.5f;
    float ay1 = ay - ah * 0.5f, ay2 = ay + ah * 0.5f;
    float bx1 = bx - bw * 0.5f, bx2 = bx + bw * 0.5f;
    float by1 = by - bh * 0.5f, by2 = by + bh * 0.5f;
    float iw = fmaxf(fminf(ax2, bx2) - fmaxf(ax1, bx1), 0.0f);
    float ih = fmaxf(fminf(ay2, by2) - fmaxf(ay1, by1), 0.0f);
    return iw * ih;
}

__device__ __forceinline__ void compute_chunk(const Stage& buf, int tid,
                                              float& loss_acc, float& iou_acc,
                                              float& cnt_acc) {
    const float*  P  = buf.sp + tid * PSTR;       // tid*120B -> 8B aligned
    const float2* P2 = reinterpret_cast<const float2*>(P);
    const float*  T  = buf.st + tid * TSTR;

    float tconf = T[20];
    float tx = T[21], ty = T[22], tw = T[23], th = T[24];

    // pred boxes via float2 (even float offsets)
    float2 v0 = P2[10], v1 = P2[11], v2 = P2[12], v3 = P2[13], v4 = P2[14];
    float c0 = v0.x, x0 = v0.y, y0 = v1.x, w0 = v1.y, h0 = v2.x;
    float c1 = v2.y, x1 = v3.x, y1 = v3.y, w1 = v4.x, h1 = v4.y;

    float ta = tw * th;   // target area (>= 0)

    float in0 = inter_area(x0, y0, w0, h0, tx, ty, tw, th);
    float in1 = inter_area(x1, y1, w1, h1, tx, ty, tw, th);
    float u0 = fabsf(w0 * h0) + ta - in0 + 1e-6f;
    float u1 = fabsf(w1 * h1) + ta - in1 + 1e-6f;

    // argmax w/o division: i1 > i0  <=>  in1*u0 > in0*u1  (u0,u1 > 0)
    bool sel1 = (in1 * u0 > in0 * u1);
    float in_s = sel1 ? in1 : in0;
    float u_s  = sel1 ? u1 : u0;
    float ib   = in_s * frcp_approx(u_s);

    float pcf = sel1 ? c1 : c0;
    float px  = sel1 ? x1 : x0;
    float py  = sel1 ? y1 : y0;
    float pw  = sel1 ? w1 : w0;
    float ph  = sel1 ? h1 : h0;

    float dx = tx - px, dy = ty - py;
    float center = dx * dx + dy * dy;

    // (sqrt(a)-sqrt(b))^2 = a + b - 2*sqrt(a*b)
    float apw = fabsf(pw), aph = fabsf(ph);
    float wh = (tw + apw - 2.0f * fsqrt_approx(tw * apw))
             + (th + aph - 2.0f * fsqrt_approx(th * aph));

    float dc = tconf - pcf;
    float confsq = dc * dc;

    float cls = 0.0f;
    #pragma unroll
    for (int k = 0; k < 10; k++) {
        float2 p = P2[k];
        float d0 = p.x - T[2 * k];
        float d1 = p.y - T[2 * k + 1];
        cls = fmaf(d0, d0, cls);
        cls = fmaf(d1, d1, cls);
    }

    float obj = (tconf == 1.0f) ? 1.0f : 0.0f;
    loss_acc += obj * (5.0f * (center + wh) + confsq + cls)
              + (1.0f - obj) * 0.5f * confsq;
    iou_acc  += obj * ib;
    cnt_acc  += obj;
}

__global__ __launch_bounds__(BLOCK)
void yolo_fused_kernel(const float4* __restrict__ pred4,
                       const float4* __restrict__ targ4,
                       float* __restrict__ out, int out_size) {
    __shared__ Stage buf[2];             // 56320 B
    __shared__ float red[3][BLOCK / 32];
    __shared__ unsigned int s_last;

    const int tid = threadIdx.x;
    const int bid = blockIdx.x;

    float loss_acc = 0.0f;
    float iou_acc  = 0.0f;
    float cnt_acc  = 0.0f;

    // contiguous range; first NEXTRA blocks take 6 chunks, rest take 5
    const int nb   = (bid < NEXTRA) ? 6 : 5;
    const int base = (bid < NEXTRA) ? bid * 6 : NEXTRA * 6 + (bid - NEXTRA) * 5;

    int cur = 0;
    stage_chunk(buf[0], base, pred4, targ4, tid);

    #pragma unroll 1
    for (int k = 0; k < nb; k++) {
        if (k + 1 < nb) {
            stage_chunk(buf[cur ^ 1], base + k + 1, pred4, targ4, tid);
            cp_wait<1>();   // oldest group (current buffer) done
        } else {
            cp_wait<0>();
        }
        __syncthreads();    // publish cp.async results to all threads

        compute_chunk(buf[cur], tid, loss_acc, iou_acc, cnt_acc);

        __syncthreads();    // all threads done reading buf[cur] before refill
        cur ^= 1;
    }

    // warp reduction
    #pragma unroll
    for (int o = 16; o > 0; o >>= 1) {
        loss_acc += __shfl_xor_sync(0xFFFFFFFFu, loss_acc, o);
        iou_acc  += __shfl_xor_sync(0xFFFFFFFFu, iou_acc, o);
        cnt_acc  += __shfl_xor_sync(0xFFFFFFFFu, cnt_acc, o);
    }
    int w = tid >> 5, l = tid & 31;
    if (l == 0) {
        red[0][w] = loss_acc;
        red[1][w] = iou_acc;
        red[2][w] = cnt_acc;
    }
    __syncthreads();
    if (tid == 0) {
        float a = 0.0f, b = 0.0f, cc = 0.0f;
        #pragma unroll
        for (int i = 0; i < BLOCK / 32; i++) {
            a  += red[0][i];
            b  += red[1][i];
            cc += red[2][i];
        }
        atomicAdd(&g_acc[0], a);
        atomicAdd(&g_acc[1], b);
        atomicAdd(&g_acc[2], cc);
        __threadfence();
        unsigned int prev = atomicAdd(&g_count, 1u);
        s_last = (prev == (unsigned int)(gridDim.x - 1)) ? 1u : 0u;
    }
    __syncthreads();

    // Last block finalizes and resets accumulators (graph-replay safe).
    if (s_last && tid == 0) {
        __threadfence();
        float a  = atomicAdd(&g_acc[0], 0.0f);
        float b  = atomicAdd(&g_acc[1], 0.0f);
        float cc = atomicAdd(&g_acc[2], 0.0f);
        out[0] = a;
        if (out_size > 1) out[1] = b / fmaxf(cc, 1.0f);
        g_acc[0] = 0.0f;
        g_acc[1] = 0.0f;
        g_acc[2] = 0.0f;
        g_count  = 0u;
        __threadfence();
    }
}

extern "C" void kernel_launch(void* const* d_in, const int* in_sizes, int n_in,
                              void* d_out, int out_size) {
    const float4* pred4 = (const float4*)d_in[0];
    const float4* targ4 = (const float4*)d_in[1];
    float* out = (float*)d_out;

    yolo_fused_kernel<<<GRID, BLOCK>>>(pred4, targ4, out, out_size);
}

// round 16
// speedup vs baseline: 1.1629x; 1.1629x over previous
#include <cuda_runtime.h>
#include <cstdint>

// Problem constants
#define SS 7
#define CC 20
#define PSTR 30          // pred floats per cell  (2*5 + 20)
#define TSTR 25          // target floats per cell (20 + 1 + 4)
#define BATCH 8192
#define NCELL (BATCH * SS * SS)      // 401408
#define BLOCK 128
#define NCHUNK (NCELL / BLOCK)       // 3136 (exact)
#define PRED4_PER_CHUNK (BLOCK * PSTR / 4)   // 960
#define TARG4_PER_CHUNK (BLOCK * TSTR / 4)   // 800
// 444 = 3 x 148: exactly 3 blocks per SM -> perfectly equal per-SM work.
// 3136 = 444*7 + 28; blocks 0..27 (28 distinct SMs under classic placement)
// take 8 contiguous chunks, the rest take 7 -> the residual +1 chunk drains
// on 28 SMs in parallel. Contiguous ranges give each block one sequential
// ~300KB stream (DRAM row locality + L2::256B prefetch effectiveness).
// Measured champion: 12.99us = 6.8TB/s (~85% of spec, ~93% of achievable).
#define GRID 444
#define NEXTRA 28                    // blocks with 8 chunks

// global accumulators: loss, sum(iou*obj), sum(obj).
// Zero at module load; last block resets after finalize -> graph-replayable.
__device__ float g_acc[3];
__device__ unsigned int g_count;

// 16B async copy with 256B L2 prefetch hint (sequential stream friendly)
__device__ __forceinline__ void cp_async16(void* smem_dst, const void* gmem_src) {
    uint32_t s = (uint32_t)__cvta_generic_to_shared(smem_dst);
    asm volatile("cp.async.cg.shared.global.L2::256B [%0], [%1], 16;\n"
                 :: "r"(s), "l"(gmem_src));
}
__device__ __forceinline__ void cp_commit() {
    asm volatile("cp.async.commit_group;\n" ::: "memory");
}
template <int N>
__device__ __forceinline__ void cp_wait() {
    asm volatile("cp.async.wait_group %0;\n" :: "n"(N) : "memory");
}

// single-instruction MUFU approximations (flag-independent)
__device__ __forceinline__ float fsqrt_approx(float x) {
    float r;
    asm("sqrt.approx.f32 %0, %1;" : "=f"(r) : "f"(x));
    return r;
}
__device__ __forceinline__ float frcp_approx(float x) {
    float r;
    asm("rcp.approx.f32 %0, %1;" : "=f"(r) : "f"(x));
    return r;
}

struct __align__(16) Stage {
    float sp[BLOCK * PSTR];   // 15360 B
    float st[BLOCK * TSTR];   // 12800 B
};

__device__ __forceinline__ void stage_chunk(Stage& buf, int chunk,
                                            const float4* __restrict__ pred4,
                                            const float4* __restrict__ targ4,
                                            int tid) {
    const float4* pc = pred4 + (size_t)chunk * PRED4_PER_CHUNK;
    const float4* tc = targ4 + (size_t)chunk * TARG4_PER_CHUNK;
    float4* sp4 = reinterpret_cast<float4*>(buf.sp);
    float4* st4 = reinterpret_cast<float4*>(buf.st);
    #pragma unroll
    for (int i = tid; i < PRED4_PER_CHUNK; i += BLOCK)
        cp_async16(&sp4[i], &pc[i]);
    #pragma unroll
    for (int i = tid; i < TARG4_PER_CHUNK; i += BLOCK)
        cp_async16(&st4[i], &tc[i]);
    cp_commit();
}

// intersection area of two xywh boxes (no division)
__device__ __forceinline__ float inter_area(float ax, float ay, float aw, float ah,
                                            float bx, float by, float bw, float bh) {
    float ax1 = ax - aw * 0.5f, ax2 = ax + aw * 0.5f;
    float ay1 = ay - ah * 0.5f, ay2 = ay + ah * 0.5f;
    float bx1 = bx - bw * 0.5f, bx2 = bx + bw * 0.5f;
    float by1 = by - bh * 0.5f, by2 = by + bh * 0.5f;
    float iw = fmaxf(fminf(ax2, bx2) - fmaxf(ax1, bx1), 0.0f);
    float ih = fmaxf(fminf(ay2, by2) - fmaxf(ay1, by1), 0.0f);
    return iw * ih;
}

__device__ __forceinline__ void compute_chunk(const Stage& buf, int tid,
                                              float& loss_acc, float& iou_acc,
                                              float& cnt_acc) {
    const float*  P  = buf.sp + tid * PSTR;       // tid*120B -> 8B aligned
    const float2* P2 = reinterpret_cast<const float2*>(P);
    const float*  T  = buf.st + tid * TSTR;

    float tconf = T[20];
    float tx = T[21], ty = T[22], tw = T[23], th = T[24];

    // pred boxes via float2 (even float offsets)
    float2 v0 = P2[10], v1 = P2[11], v2 = P2[12], v3 = P2[13], v4 = P2[14];
    float c0 = v0.x, x0 = v0.y, y0 = v1.x, w0 = v1.y, h0 = v2.x;
    float c1 = v2.y, x1 = v3.x, y1 = v3.y, w1 = v4.x, h1 = v4.y;

    float ta = tw * th;   // target area (>= 0)

    float in0 = inter_area(x0, y0, w0, h0, tx, ty, tw, th);
    float in1 = inter_area(x1, y1, w1, h1, tx, ty, tw, th);
    float u0 = fabsf(w0 * h0) + ta - in0 + 1e-6f;
    float u1 = fabsf(w1 * h1) + ta - in1 + 1e-6f;

    // argmax w/o division: i1 > i0  <=>  in1*u0 > in0*u1  (u0,u1 > 0)
    bool sel1 = (in1 * u0 > in0 * u1);
    float in_s = sel1 ? in1 : in0;
    float u_s  = sel1 ? u1 : u0;
    float ib   = in_s * frcp_approx(u_s);

    float pcf = sel1 ? c1 : c0;
    float px  = sel1 ? x1 : x0;
    float py  = sel1 ? y1 : y0;
    float pw  = sel1 ? w1 : w0;
    float ph  = sel1 ? h1 : h0;

    float dx = tx - px, dy = ty - py;
    float center = dx * dx + dy * dy;

    // (sqrt(a)-sqrt(b))^2 = a + b - 2*sqrt(a*b)
    float apw = fabsf(pw), aph = fabsf(ph);
    float wh = (tw + apw - 2.0f * fsqrt_approx(tw * apw))
             + (th + aph - 2.0f * fsqrt_approx(th * aph));

    float dc = tconf - pcf;
    float confsq = dc * dc;

    float cls = 0.0f;
    #pragma unroll
    for (int k = 0; k < 10; k++) {
        float2 p = P2[k];
        float d0 = p.x - T[2 * k];
        float d1 = p.y - T[2 * k + 1];
        cls = fmaf(d0, d0, cls);
        cls = fmaf(d1, d1, cls);
    }

    float obj = (tconf == 1.0f) ? 1.0f : 0.0f;
    loss_acc += obj * (5.0f * (center + wh) + confsq + cls)
              + (1.0f - obj) * 0.5f * confsq;
    iou_acc  += obj * ib;
    cnt_acc  += obj;
}

__global__ __launch_bounds__(BLOCK)
void yolo_fused_kernel(const float4* __restrict__ pred4,
                       const float4* __restrict__ targ4,
                       float* __restrict__ out, int out_size) {
    __shared__ Stage buf[2];             // 56320 B
    __shared__ float red[3][BLOCK / 32];
    __shared__ unsigned int s_last;

    const int tid = threadIdx.x;
    const int bid = blockIdx.x;

    float loss_acc = 0.0f;
    float iou_acc  = 0.0f;
    float cnt_acc  = 0.0f;

    // contiguous range; first NEXTRA blocks take 8 chunks, rest take 7
    const int nb   = (bid < NEXTRA) ? 8 : 7;
    const int base = (bid < NEXTRA) ? bid * 8 : NEXTRA * 8 + (bid - NEXTRA) * 7;

    int cur = 0;
    stage_chunk(buf[0], base, pred4, targ4, tid);

    #pragma unroll 1
    for (int k = 0; k < nb; k++) {
        if (k + 1 < nb) {
            stage_chunk(buf[cur ^ 1], base + k + 1, pred4, targ4, tid);
            cp_wait<1>();   // oldest group (current buffer) done
        } else {
            cp_wait<0>();
        }
        __syncthreads();    // publish cp.async results to all threads

        compute_chunk(buf[cur], tid, loss_acc, iou_acc, cnt_acc);

        __syncthreads();    // all threads done reading buf[cur] before refill
        cur ^= 1;
    }

    // warp reduction
    #pragma unroll
    for (int o = 16; o > 0; o >>= 1) {
        loss_acc += __shfl_xor_sync(0xFFFFFFFFu, loss_acc, o);
        iou_acc  += __shfl_xor_sync(0xFFFFFFFFu, iou_acc, o);
        cnt_acc  += __shfl_xor_sync(0xFFFFFFFFu, cnt_acc, o);
    }
    int w = tid >> 5, l = tid & 31;
    if (l == 0) {
        red[0][w] = loss_acc;
        red[1][w] = iou_acc;
        red[2][w] = cnt_acc;
    }
    __syncthreads();
    if (tid == 0) {
        float a = 0.0f, b = 0.0f, cc = 0.0f;
        #pragma unroll
        for (int i = 0; i < BLOCK / 32; i++) {
            a  += red[0][i];
            b  += red[1][i];
            cc += red[2][i];
        }
        atomicAdd(&g_acc[0], a);
        atomicAdd(&g_acc[1], b);
        atomicAdd(&g_acc[2], cc);
        __threadfence();
        unsigned int prev = atomicAdd(&g_count, 1u);
        s_last = (prev == (unsigned int)(gridDim.x - 1)) ? 1u : 0u;
    }
    __syncthreads();

    // Last block finalizes and resets accumulators (graph-replay safe).
    if (s_last && tid == 0) {
        __threadfence();
        float a  = atomicAdd(&g_acc[0], 0.0f);
        float b  = atomicAdd(&g_acc[1], 0.0f);
        float cc = atomicAdd(&g_acc[2], 0.0f);
        out[0] = a;
        if (out_size > 1) out[1] = b / fmaxf(cc, 1.0f);
        g_acc[0] = 0.0f;
        g_acc[1] = 0.0f;
        g_acc[2] = 0.0f;
        g_count  = 0u;
        __threadfence();
    }
}

extern "C" void kernel_launch(void* const* d_in, const int* in_sizes, int n_in,
                              void* d_out, int out_size) {
    const float4* pred4 = (const float4*)d_in[0];
    const float4* targ4 = (const float4*)d_in[1];
    float* out = (float*)d_out;

    yolo_fused_kernel<<<GRID, BLOCK>>>(pred4, targ4, out, out_size);
}